// round 14
// baseline (speedup 1.0000x reference)
#include <cuda_runtime.h>
#include <cstdint>
#include <cstddef>

#define Bb  4
#define Ss  2048
#define Dd  512
#define Hh  8
#define DHh 64
#define Nn  (Bb*Ss)

// ---------------- device scratch (no allocations allowed) ----------------
__device__ float g_Qt[Bb*Hh*DHh*Ss];    // [bh][d][s]  (transposed for flash)
__device__ float g_Kt[Bb*Hh*DHh*Ss];    // [bh][d][s]
__device__ float g_V [Bb*Hh*Ss*DHh];    // [bh][s][d]
__device__ float g_ctx[(size_t)Nn*Dd];  // [b*s][d]
__device__ float g_meanV[Bb*Hh*DHh];    // [bh][d]

// ---------------- 64x64 output tile GEMM over K=512 ----------------------
// 256 threads, thread (ty,tx) owns 4x4 microtile. A read via broadcast
// float4 (k-contiguous), B read via float4 — FMA-pipe bound.
__device__ __forceinline__ void gemm64(const float* __restrict__ A,
                                       const float* __restrict__ W,
                                       int m0, int n0,
                                       float (&acc)[4][4],
                                       float* Xs, float* Bs) {
  const int tid = threadIdx.x;
  const int ty = tid >> 4, tx = tid & 15;
  const int lr = ty, lc = tx << 2;
  for (int kb = 0; kb < Dd; kb += 64) {
#pragma unroll
    for (int r = 0; r < 4; r++) {
      *(float4*)&Xs[(lr + 16*r)*68 + lc] =
          *(const float4*)&A[(size_t)(m0 + lr + 16*r)*Dd + kb + lc];
      *(float4*)&Bs[(lr + 16*r)*68 + lc] =
          *(const float4*)&W[(size_t)(kb + lr + 16*r)*Dd + n0 + lc];
    }
    __syncthreads();
#pragma unroll
    for (int kk = 0; kk < 64; kk += 4) {
      float a0[4], a1[4], a2[4], a3[4];
      *(float4*)a0 = *(const float4*)&Xs[(ty*4+0)*68 + kk];
      *(float4*)a1 = *(const float4*)&Xs[(ty*4+1)*68 + kk];
      *(float4*)a2 = *(const float4*)&Xs[(ty*4+2)*68 + kk];
      *(float4*)a3 = *(const float4*)&Xs[(ty*4+3)*68 + kk];
#pragma unroll
      for (int u = 0; u < 4; u++) {
        float4 bv = *(const float4*)&Bs[(kk+u)*68 + (tx<<2)];
        acc[0][0] = fmaf(a0[u], bv.x, acc[0][0]);
        acc[0][1] = fmaf(a0[u], bv.y, acc[0][1]);
        acc[0][2] = fmaf(a0[u], bv.z, acc[0][2]);
        acc[0][3] = fmaf(a0[u], bv.w, acc[0][3]);
        acc[1][0] = fmaf(a1[u], bv.x, acc[1][0]);
        acc[1][1] = fmaf(a1[u], bv.y, acc[1][1]);
        acc[1][2] = fmaf(a1[u], bv.z, acc[1][2]);
        acc[1][3] = fmaf(a1[u], bv.w, acc[1][3]);
        acc[2][0] = fmaf(a2[u], bv.x, acc[2][0]);
        acc[2][1] = fmaf(a2[u], bv.y, acc[2][1]);
        acc[2][2] = fmaf(a2[u], bv.z, acc[2][2]);
        acc[2][3] = fmaf(a2[u], bv.w, acc[2][3]);
        acc[3][0] = fmaf(a3[u], bv.x, acc[3][0]);
        acc[3][1] = fmaf(a3[u], bv.y, acc[3][1]);
        acc[3][2] = fmaf(a3[u], bv.z, acc[3][2]);
        acc[3][3] = fmaf(a3[u], bv.w, acc[3][3]);
      }
    }
    __syncthreads();
  }
}

// ---------------- QKV projection ------------------------------------------
// grid (128, 8, 3). z selects weight + output layout (Q/K transposed).
__global__ __launch_bounds__(256, 2)
void proj_kernel(const float* __restrict__ X,
                 const float* __restrict__ Wq,
                 const float* __restrict__ Wk,
                 const float* __restrict__ Wv) {
  __shared__ __align__(16) float Xs[64*68];
  __shared__ __align__(16) float Bs[64*68];
  const int z = blockIdx.z;
  const float* W = (z == 0) ? Wq : ((z == 1) ? Wk : Wv);
  const int m0 = blockIdx.x * 64, n0 = blockIdx.y * 64;
  float acc[4][4] = {};
  gemm64(X, W, m0, n0, acc, Xs, Bs);

  const int tid = threadIdx.x, ty = tid >> 4, tx = tid & 15;
  const int b  = m0 >> 11;            // S=2048
  const int s0 = m0 & (Ss - 1);
  const int bh = b * Hh + (n0 >> 6);  // head = column-block
  if (z == 2) {
#pragma unroll
    for (int i = 0; i < 4; i++) {
      float4 v = make_float4(acc[i][0], acc[i][1], acc[i][2], acc[i][3]);
      *(float4*)&g_V[((size_t)bh*Ss + s0 + ty*4 + i)*DHh + tx*4] = v;
    }
  } else {
    float* dst = (z == 0) ? g_Qt : g_Kt;
#pragma unroll
    for (int j = 0; j < 4; j++) {
      float4 v = make_float4(acc[0][j], acc[1][j], acc[2][j], acc[3][j]);
      *(float4*)&dst[((size_t)bh*DHh + tx*4 + j)*Ss + s0 + ty*4] = v;
    }
  }
}

// ---------------- mean of V over all keys (for fully-masked query rows) ---
__global__ void meanv_kernel() {
  __shared__ float red[256];
  const int bh = blockIdx.x, t = threadIdx.x;
  const int d = t & 63, c = t >> 6;          // 4 chunks of 512 s
  const float* vp = &g_V[((size_t)bh*Ss + c*512)*DHh + d];
  float sum = 0.f;
#pragma unroll 8
  for (int s = 0; s < 512; s++) sum += vp[(size_t)s*DHh];
  red[t] = sum;
  __syncthreads();
  if (t < 64)
    g_meanV[bh*DHh + t] =
        (red[t] + red[t+64] + red[t+128] + red[t+192]) * (1.f/2048.f);
}

// ---------------- causal flash attention ----------------------------------
// grid (32 qtiles, 32 bh), 256 threads, 64x64 tiles, online softmax.
#define FLASH_SMEM_BYTES ((4*64*68 + 64)*4)

__global__ __launch_bounds__(256, 2)
void flash_kernel(const int* __restrict__ tm) {
  extern __shared__ __align__(16) float sm[];
  float* Qs  = sm;                 // [d][q] stride 68
  float* Ks  = Qs + 64*68;         // [d][k] stride 68
  float* Vs  = Ks + 64*68;         // [k][d] stride 68
  float* Ps  = Vs + 64*68;         // [q][k] stride 68
  float* tmk = Ps + 64*68;         // [64]

  const int bh = blockIdx.y, b = bh >> 3, h = bh & 7;
  const int qt = (int)gridDim.x - 1 - (int)blockIdx.x;  // heavy blocks first
  const int q0 = qt * 64;
  const int tid = threadIdx.x, ty = tid >> 4, tx = tid & 15;
  const int lr = ty, lc = tx << 2;

  // Q tile, already transposed in global: [d][q]
#pragma unroll
  for (int r = 0; r < 4; r++) {
    const int d = lr + 16*r;
    *(float4*)&Qs[d*68 + lc] =
        *(const float4*)&g_Qt[((size_t)bh*DHh + d)*Ss + q0 + lc];
  }
  int tmq[4];
#pragma unroll
  for (int i = 0; i < 4; i++) tmq[i] = tm[b*Ss + q0 + ty*4 + i];

  float o[4][4] = {};
  float mi[4] = {-1e30f, -1e30f, -1e30f, -1e30f};
  float li[4] = {0.f, 0.f, 0.f, 0.f};

  for (int kt = 0; kt <= qt; kt++) {
    __syncthreads();   // previous PV done before overwriting Ks/Vs/tmk
    const int k0 = kt * 64;
#pragma unroll
    for (int r = 0; r < 4; r++) {
      const int rr = lr + 16*r;
      *(float4*)&Ks[rr*68 + lc] =
          *(const float4*)&g_Kt[((size_t)bh*DHh + rr)*Ss + k0 + lc];
      *(float4*)&Vs[rr*68 + lc] =
          *(const float4*)&g_V[((size_t)bh*Ss + k0 + rr)*DHh + lc];
    }
    if (tid < 64) tmk[tid] = (float)tm[b*Ss + k0 + tid];
    __syncthreads();

    // S = Q K^T
    float sacc[4][4] = {};
#pragma unroll 8
    for (int kk = 0; kk < 64; kk++) {
      float4 qv = *(const float4*)&Qs[kk*68 + (ty<<2)];
      float4 kv = *(const float4*)&Ks[kk*68 + (tx<<2)];
      sacc[0][0] = fmaf(qv.x, kv.x, sacc[0][0]);
      sacc[0][1] = fmaf(qv.x, kv.y, sacc[0][1]);
      sacc[0][2] = fmaf(qv.x, kv.z, sacc[0][2]);
      sacc[0][3] = fmaf(qv.x, kv.w, sacc[0][3]);
      sacc[1][0] = fmaf(qv.y, kv.x, sacc[1][0]);
      sacc[1][1] = fmaf(qv.y, kv.y, sacc[1][1]);
      sacc[1][2] = fmaf(qv.y, kv.z, sacc[1][2]);
      sacc[1][3] = fmaf(qv.y, kv.w, sacc[1][3]);
      sacc[2][0] = fmaf(qv.z, kv.x, sacc[2][0]);
      sacc[2][1] = fmaf(qv.z, kv.y, sacc[2][1]);
      sacc[2][2] = fmaf(qv.z, kv.z, sacc[2][2]);
      sacc[2][3] = fmaf(qv.z, kv.w, sacc[2][3]);
      sacc[3][0] = fmaf(qv.w, kv.x, sacc[3][0]);
      sacc[3][1] = fmaf(qv.w, kv.y, sacc[3][1]);
      sacc[3][2] = fmaf(qv.w, kv.z, sacc[3][2]);
      sacc[3][3] = fmaf(qv.w, kv.w, sacc[3][3]);
    }

    float tk[4];
#pragma unroll
    for (int j = 0; j < 4; j++) tk[j] = tmk[tx*4 + j];

    // masked online softmax per row
#pragma unroll
    for (int i = 0; i < 4; i++) {
      const int qg = q0 + ty*4 + i;
      float sv[4];
      float rmax = -1e30f;
#pragma unroll
      for (int j = 0; j < 4; j++) {
        const int kg = k0 + tx*4 + j;
        const bool valid = (kg <= qg) && (tk[j] > 0.5f);
        sv[j] = valid ? sacc[i][j] * 0.125f : -1e30f;  // 1/sqrt(64)
        rmax = fmaxf(rmax, sv[j]);
      }
#pragma unroll
      for (int off = 1; off < 16; off <<= 1)
        rmax = fmaxf(rmax, __shfl_xor_sync(0xffffffffu, rmax, off));
      const float mnew = fmaxf(mi[i], rmax);
      float p[4];
      float rsum = 0.f;
#pragma unroll
      for (int j = 0; j < 4; j++) {
        // guard: fully-masked tile (mnew==-1e30) must contribute 0, not exp(0)
        p[j] = (sv[j] > -1e29f) ? __expf(sv[j] - mnew) : 0.f;
        rsum += p[j];
      }
#pragma unroll
      for (int off = 1; off < 16; off <<= 1)
        rsum += __shfl_xor_sync(0xffffffffu, rsum, off);
      const float corr = __expf(mi[i] - mnew);
      li[i] = li[i] * corr + rsum;
#pragma unroll
      for (int j = 0; j < 4; j++) o[i][j] *= corr;
      mi[i] = mnew;
      *(float4*)&Ps[(ty*4+i)*68 + (tx<<2)] = make_float4(p[0], p[1], p[2], p[3]);
    }
    __syncthreads();

    // O += P V
#pragma unroll 4
    for (int k = 0; k < 64; k += 4) {
      float p0[4], p1[4], p2[4], p3[4];
      *(float4*)p0 = *(const float4*)&Ps[(ty*4+0)*68 + k];
      *(float4*)p1 = *(const float4*)&Ps[(ty*4+1)*68 + k];
      *(float4*)p2 = *(const float4*)&Ps[(ty*4+2)*68 + k];
      *(float4*)p3 = *(const float4*)&Ps[(ty*4+3)*68 + k];
#pragma unroll
      for (int u = 0; u < 4; u++) {
        float4 vv = *(const float4*)&Vs[(k+u)*68 + (tx<<2)];
        o[0][0] = fmaf(p0[u], vv.x, o[0][0]);
        o[0][1] = fmaf(p0[u], vv.y, o[0][1]);
        o[0][2] = fmaf(p0[u], vv.z, o[0][2]);
        o[0][3] = fmaf(p0[u], vv.w, o[0][3]);
        o[1][0] = fmaf(p1[u], vv.x, o[1][0]);
        o[1][1] = fmaf(p1[u], vv.y, o[1][1]);
        o[1][2] = fmaf(p1[u], vv.z, o[1][2]);
        o[1][3] = fmaf(p1[u], vv.w, o[1][3]);
        o[2][0] = fmaf(p2[u], vv.x, o[2][0]);
        o[2][1] = fmaf(p2[u], vv.y, o[2][1]);
        o[2][2] = fmaf(p2[u], vv.z, o[2][2]);
        o[2][3] = fmaf(p2[u], vv.w, o[2][3]);
        o[3][0] = fmaf(p3[u], vv.x, o[3][0]);
        o[3][1] = fmaf(p3[u], vv.y, o[3][1]);
        o[3][2] = fmaf(p3[u], vv.z, o[3][2]);
        o[3][3] = fmaf(p3[u], vv.w, o[3][3]);
      }
    }
  }

  // epilogue: normalize; fully-masked queries get uniform softmax = meanV
#pragma unroll
  for (int i = 0; i < 4; i++) {
    const int s = q0 + ty*4 + i;
    float4 res;
    if (tmq[i] != 0) {
      const float inv = 1.f / li[i];
      res = make_float4(o[i][0]*inv, o[i][1]*inv, o[i][2]*inv, o[i][3]*inv);
    } else {
      res = *(const float4*)&g_meanV[bh*DHh + tx*4];
    }
    *(float4*)&g_ctx[((size_t)b*Ss + s)*Dd + h*DHh + tx*4] = res;
  }
}

// ---------------- output projection ---------------------------------------
__global__ __launch_bounds__(256, 2)
void outproj_kernel(const float* __restrict__ Wo, float* __restrict__ out) {
  __shared__ __align__(16) float Xs[64*68];
  __shared__ __align__(16) float Bs[64*68];
  const int m0 = blockIdx.x * 64, n0 = blockIdx.y * 64;
  float acc[4][4] = {};
  gemm64(g_ctx, Wo, m0, n0, acc, Xs, Bs);
  const int tid = threadIdx.x, ty = tid >> 4, tx = tid & 15;
#pragma unroll
  for (int i = 0; i < 4; i++) {
    float4 v = make_float4(acc[i][0], acc[i][1], acc[i][2], acc[i][3]);
    *(float4*)&out[(size_t)(m0 + ty*4 + i)*Dd + n0 + tx*4] = v;
  }
}

// ---------------- launch ---------------------------------------------------
extern "C" void kernel_launch(void* const* d_in, const int* in_sizes, int n_in,
                              void* d_out, int out_size) {
  (void)in_sizes; (void)n_in; (void)out_size;
  const float* emb = (const float*)d_in[0];
  const int*   tm  = (const int*)  d_in[1];
  const float* Wq  = (const float*)d_in[2];
  const float* Wk  = (const float*)d_in[3];
  const float* Wv  = (const float*)d_in[4];
  const float* Wo  = (const float*)d_in[5];
  float* out = (float*)d_out;

  cudaFuncSetAttribute(flash_kernel,
                       cudaFuncAttributeMaxDynamicSharedMemorySize,
                       FLASH_SMEM_BYTES);

  proj_kernel<<<dim3(Nn/64, Dd/64, 3), 256>>>(emb, Wq, Wk, Wv);
  meanv_kernel<<<Bb*Hh, 256>>>();
  flash_kernel<<<dim3(Ss/64, Bb*Hh), 256, FLASH_SMEM_BYTES>>>(tm);
  outproj_kernel<<<dim3(Nn/64, Dd/64), 256>>>(Wo, out);
}